// round 5
// baseline (speedup 1.0000x reference)
#include <cuda_runtime.h>
#include <math.h>

#define BB 64
#define HH 512
#define EE 512
#define SS 2048
#define VV 32000
#define NSPLIT 32
#define SPLIT_S (SS / NSPLIT)
#define NCLS_TILES 250          // 32000 / 128
#define MEGA_BLOCKS (NCLS_TILES + NSPLIT * BB)

#define FMA_F32X2(d, a, b, c) \
    asm("fma.rn.f32x2 %0, %1, %2, %3;" : "=l"(d) : "l"(a), "l"(b), "l"(c))
#define PACK_BCAST(d, f) \
    asm("mov.b64 %0, {%1, %1};" : "=l"(d) : "r"(__float_as_uint(f)))

typedef unsigned long long u64;

// ---------------- scratch ----------------
__device__ float g_x[BB * EE];
__device__ float g_gi[BB * 3 * HH];
__device__ float g_gh[BB * 3 * HH];
__device__ float g_A[BB * 2 * HH];          // [h_new | context]
__device__ float g_u[BB * HH];
__device__ float g_pctx[(size_t)NSPLIT * BB * HH];
__device__ float g_pml[NSPLIT * BB * 2];

// ---------------- K0: embedding gather + ReLU ----------------
__global__ void k_embed(const int* __restrict__ idx, const float* __restrict__ emb) {
    int b = blockIdx.x, t = threadIdx.x;
    int row = idx[b];
    float4 v = ((const float4*)(emb + (size_t)row * EE))[t];
    v.x = fmaxf(v.x, 0.f); v.y = fmaxf(v.y, 0.f);
    v.z = fmaxf(v.z, 0.f); v.w = fmaxf(v.w, 0.f);
    ((float4*)(g_x + b * EE))[t] = v;
}

// ---------------- gemmN64: 64M x 64N tile, 128 thr, full K, f32x2 ----------
// BT=true : W[n][k].  BT=false: W[k][n].  No atomics.
template<bool BT, bool HASB>
__device__ __forceinline__ void gemmN64(const float* __restrict__ A, int lda,
                                        const float* __restrict__ W, int ldw,
                                        const float* __restrict__ bias,
                                        float* __restrict__ C, int ldc,
                                        int K, int n0) {
    __shared__ float As[2][16][68];
    __shared__ float Bs[2][16][68];
    const int tid = threadIdx.x;
    const int mt = (tid >> 4) * 8;   // 0..56
    const int nt = (tid & 15) * 4;   // 0..60

    u64 acc2[8][2];
#pragma unroll
    for (int i = 0; i < 8; i++) { acc2[i][0] = 0ull; acc2[i][1] = 0ull; }

    float4 ra[2], rb[2];
    auto ldG = [&](int k0) {
#pragma unroll
        for (int r = 0; r < 2; r++) {
            int i = tid + r * 128;
            int m = i >> 2, kq = (i & 3) * 4;
            ra[r] = *(const float4*)(A + (size_t)m * lda + k0 + kq);
        }
#pragma unroll
        for (int r = 0; r < 2; r++) {
            int i = tid + r * 128;
            if (BT) {
                int n = i >> 2, kq = (i & 3) * 4;
                rb[r] = *(const float4*)(W + (size_t)(n0 + n) * ldw + k0 + kq);
            } else {
                int k = i >> 4, nq = (i & 15) * 4;
                rb[r] = *(const float4*)(W + (size_t)(k0 + k) * ldw + n0 + nq);
            }
        }
    };
    auto stS = [&](int buf) {
#pragma unroll
        for (int r = 0; r < 2; r++) {
            int i = tid + r * 128;
            int m = i >> 2, kq = (i & 3) * 4;
            As[buf][kq + 0][m] = ra[r].x; As[buf][kq + 1][m] = ra[r].y;
            As[buf][kq + 2][m] = ra[r].z; As[buf][kq + 3][m] = ra[r].w;
        }
#pragma unroll
        for (int r = 0; r < 2; r++) {
            int i = tid + r * 128;
            if (BT) {
                int n = i >> 2, kq = (i & 3) * 4;
                Bs[buf][kq + 0][n] = rb[r].x; Bs[buf][kq + 1][n] = rb[r].y;
                Bs[buf][kq + 2][n] = rb[r].z; Bs[buf][kq + 3][n] = rb[r].w;
            } else {
                int k = i >> 4, nq = (i & 15) * 4;
                *(float4*)&Bs[buf][k][nq] = rb[r];
            }
        }
    };

    ldG(0);
    stS(0);
    __syncthreads();
    const int ntile = K / 16;
#pragma unroll 1
    for (int t = 0; t < ntile; t++) {
        const int cur = t & 1;
        if (t + 1 < ntile) ldG((t + 1) * 16);
#pragma unroll
        for (int kk = 0; kk < 16; kk++) {
            float4 a0 = *(const float4*)&As[cur][kk][mt];
            float4 a1 = *(const float4*)&As[cur][kk][mt + 4];
            float4 bv = *(const float4*)&Bs[cur][kk][nt];
            u64 pb0 = *(u64*)&bv.x, pb1 = *(u64*)&bv.z;
            float av[8] = {a0.x, a0.y, a0.z, a0.w, a1.x, a1.y, a1.z, a1.w};
#pragma unroll
            for (int i = 0; i < 8; i++) {
                u64 pa;
                PACK_BCAST(pa, av[i]);
                FMA_F32X2(acc2[i][0], pa, pb0, acc2[i][0]);
                FMA_F32X2(acc2[i][1], pa, pb1, acc2[i][1]);
            }
        }
        if (t + 1 < ntile) stS(cur ^ 1);
        __syncthreads();
    }

    float4 bi = make_float4(0.f, 0.f, 0.f, 0.f);
    if (HASB) bi = *(const float4*)(bias + n0 + nt);
#pragma unroll
    for (int i = 0; i < 8; i++) {
        float2 f0 = *(float2*)&acc2[i][0];
        float2 f1 = *(float2*)&acc2[i][1];
        *(float4*)(C + (size_t)(mt + i) * ldc + n0 + nt) =
            make_float4(f0.x + bi.x, f0.y + bi.y, f1.x + bi.z, f1.y + bi.w);
    }
}

// GRU gate GEMMs (bias folded): grid (24, 2)
__global__ void __launch_bounds__(128) k_gru(const float* __restrict__ h0,
        const float* __restrict__ W_ih, const float* __restrict__ W_hh,
        const float* __restrict__ b_ih, const float* __restrict__ b_hh) {
    if (blockIdx.y == 0)
        gemmN64<true, true>(g_x, EE, W_ih, EE, b_ih, g_gi, 3 * HH, EE, blockIdx.x * 64);
    else
        gemmN64<true, true>(h0, HH, W_hh, HH, b_hh, g_gh, 3 * HH, HH, blockIdx.x * 64);
}

// u = h @ W_attn (8 blocks, full K)
__global__ void __launch_bounds__(128) k_u(const float* __restrict__ Wa) {
    gemmN64<false, false>(g_A, 1024, Wa, HH, nullptr, g_u, HH, HH, blockIdx.x * 64);
}

// ---------------- GRU gate combine (biases already in gi/gh) ----------------
__global__ void k_gates(const float* __restrict__ h0, float* __restrict__ out_hidden) {
    int i = blockIdx.x * 256 + threadIdx.x;
    int b = i >> 9, h = i & 511;
    float gir = g_gi[b * 1536 + h],        ghr = g_gh[b * 1536 + h];
    float giz = g_gi[b * 1536 + 512 + h],  ghz = g_gh[b * 1536 + 512 + h];
    float gin = g_gi[b * 1536 + 1024 + h], ghn = g_gh[b * 1536 + 1024 + h];
    float r = 1.f / (1.f + __expf(-(gir + ghr)));
    float z = 1.f / (1.f + __expf(-(giz + ghz)));
    float n = tanhf(gin + r * ghn);
    float hv = (1.f - z) * n + z * h0[b * HH + h];
    g_A[b * 1024 + h] = hv;
    out_hidden[b * HH + h] = hv;
}

// ---------------- classifier half-GEMM body: 64x128 tile, 256 thr ----------
// C[m, n0+n] (+)= sum_{k<K} A[m,k]*W[n0+n,k] (+ bias). lda = ldw = 1024.
template<bool ACCUM>
__device__ __forceinline__ void cls_body(float* __restrict__ sm,
                                         const float* __restrict__ A,
                                         const float* __restrict__ W,
                                         const float* __restrict__ bias,
                                         float* __restrict__ C, int n0, int K) {
    float (*As)[16][68]  = (float(*)[16][68])sm;            // 2176 floats
    float (*Bs)[16][132] = (float(*)[16][132])(sm + 2176);  // 4224 floats
    const int tid = threadIdx.x;
    const int mt = (tid >> 4) * 4;   // 0..60
    const int nt = (tid & 15) * 8;   // 0..120

    u64 acc2[4][4];
#pragma unroll
    for (int i = 0; i < 4; i++)
#pragma unroll
        for (int j = 0; j < 4; j++) acc2[i][j] = 0ull;

    float4 ra, rb[2];
    auto ldG = [&](int k0) {
        {
            int m = tid >> 2, kq = (tid & 3) * 4;
            ra = *(const float4*)(A + (size_t)m * 1024 + k0 + kq);
        }
#pragma unroll
        for (int r = 0; r < 2; r++) {
            int i = tid + r * 256;
            int n = i >> 2, kq = (i & 3) * 4;
            rb[r] = *(const float4*)(W + (size_t)(n0 + n) * 1024 + k0 + kq);
        }
    };
    auto stS = [&](int buf) {
        {
            int m = tid >> 2, kq = (tid & 3) * 4;
            As[buf][kq + 0][m] = ra.x; As[buf][kq + 1][m] = ra.y;
            As[buf][kq + 2][m] = ra.z; As[buf][kq + 3][m] = ra.w;
        }
#pragma unroll
        for (int r = 0; r < 2; r++) {
            int i = tid + r * 256;
            int n = i >> 2, kq = (i & 3) * 4;
            Bs[buf][kq + 0][n] = rb[r].x; Bs[buf][kq + 1][n] = rb[r].y;
            Bs[buf][kq + 2][n] = rb[r].z; Bs[buf][kq + 3][n] = rb[r].w;
        }
    };

    ldG(0);
    stS(0);
    __syncthreads();
    const int ntile = K / 16;
#pragma unroll 1
    for (int t = 0; t < ntile; t++) {
        const int cur = t & 1;
        if (t + 1 < ntile) ldG((t + 1) * 16);
#pragma unroll
        for (int kk = 0; kk < 16; kk++) {
            float4 a = *(const float4*)&As[cur][kk][mt];
            float4 bv0 = *(const float4*)&Bs[cur][kk][nt];
            float4 bv1 = *(const float4*)&Bs[cur][kk][nt + 4];
            u64 pb0 = *(u64*)&bv0.x, pb1 = *(u64*)&bv0.z;
            u64 pb2 = *(u64*)&bv1.x, pb3 = *(u64*)&bv1.z;
            float av[4] = {a.x, a.y, a.z, a.w};
#pragma unroll
            for (int i = 0; i < 4; i++) {
                u64 pa;
                PACK_BCAST(pa, av[i]);
                FMA_F32X2(acc2[i][0], pa, pb0, acc2[i][0]);
                FMA_F32X2(acc2[i][1], pa, pb1, acc2[i][1]);
                FMA_F32X2(acc2[i][2], pa, pb2, acc2[i][2]);
                FMA_F32X2(acc2[i][3], pa, pb3, acc2[i][3]);
            }
        }
        if (t + 1 < ntile) stS(cur ^ 1);
        __syncthreads();
    }

#pragma unroll
    for (int i = 0; i < 4; i++) {
        float o[8];
#pragma unroll
        for (int jp = 0; jp < 4; jp++) {
            float2 f = *reinterpret_cast<float2*>(&acc2[i][jp]);
            o[2 * jp] = f.x; o[2 * jp + 1] = f.y;
        }
        size_t base = (size_t)(mt + i) * VV + n0 + nt;
        if (ACCUM) {
            float4 p0 = *(float4*)(C + base);
            float4 p1 = *(float4*)(C + base + 4);
            float4 b0 = *(const float4*)(bias + n0 + nt);
            float4 b1 = *(const float4*)(bias + n0 + nt + 4);
            *(float4*)(C + base) = make_float4(o[0] + p0.x + b0.x, o[1] + p0.y + b0.y,
                                               o[2] + p0.z + b0.z, o[3] + p0.w + b0.w);
            *(float4*)(C + base + 4) = make_float4(o[4] + p1.x + b1.x, o[5] + p1.y + b1.y,
                                                   o[6] + p1.z + b1.z, o[7] + p1.w + b1.w);
        } else {
            *(float4*)(C + base)     = make_float4(o[0], o[1], o[2], o[3]);
            *(float4*)(C + base + 4) = make_float4(o[4], o[5], o[6], o[7]);
        }
    }
}

// ---------------- attention body (warp-per-row, fp32 — proven) ----------------
__device__ __forceinline__ void attn_body(float* __restrict__ sm,
                                          const float* __restrict__ enc, int abid) {
    const int sp = abid & (NSPLIT - 1);
    const int b = abid >> 5;
    const int t = threadIdx.x;
    const int wid = t >> 5, lane = t & 31;
    float* su = sm;                    // 512
    float (*sctx)[HH] = (float(*)[HH])(sm + 512);   // 8*512
    float* sml = sm + 512 + 8 * HH;    // 16

    su[t] = g_u[b * HH + t];
    su[t + 256] = g_u[b * HH + t + 256];
    __syncthreads();

    float4 u4[4];
#pragma unroll
    for (int j = 0; j < 4; j++) u4[j] = ((const float4*)su)[lane + 32 * j];

    float m = -INFINITY, l = 0.f;
    float4 acc[4];
#pragma unroll
    for (int j = 0; j < 4; j++) acc[j] = make_float4(0.f, 0.f, 0.f, 0.f);

    const int s0 = sp * SPLIT_S;
    float4 v[4];
    {
        const float4* row = (const float4*)(enc + ((size_t)(s0 + wid) * BB + b) * HH);
#pragma unroll
        for (int j = 0; j < 4; j++) v[j] = row[lane + 32 * j];
    }

    for (int i = wid; i < SPLIT_S; i += 8) {
        float4 vn[4];
        if (i + 8 < SPLIT_S) {
            const float4* rn = (const float4*)(enc + ((size_t)(s0 + i + 8) * BB + b) * HH);
#pragma unroll
            for (int j = 0; j < 4; j++) vn[j] = rn[lane + 32 * j];
        } else {
#pragma unroll
            for (int j = 0; j < 4; j++) vn[j] = make_float4(0.f, 0.f, 0.f, 0.f);
        }
        float p = 0.f;
#pragma unroll
        for (int j = 0; j < 4; j++)
            p += v[j].x * u4[j].x + v[j].y * u4[j].y + v[j].z * u4[j].z + v[j].w * u4[j].w;
#pragma unroll
        for (int o = 16; o; o >>= 1) p += __shfl_xor_sync(0xffffffffu, p, o);

        float nm = fmaxf(m, p);
        float sc = __expf(m - nm);
        float w = __expf(p - nm);
        l = l * sc + w;
#pragma unroll
        for (int j = 0; j < 4; j++) {
            acc[j].x = acc[j].x * sc + w * v[j].x;
            acc[j].y = acc[j].y * sc + w * v[j].y;
            acc[j].z = acc[j].z * sc + w * v[j].z;
            acc[j].w = acc[j].w * sc + w * v[j].w;
        }
        m = nm;
#pragma unroll
        for (int j = 0; j < 4; j++) v[j] = vn[j];
    }

#pragma unroll
    for (int j = 0; j < 4; j++) ((float4*)sctx[wid])[lane + 32 * j] = acc[j];
    if (lane == 0) { sml[wid * 2] = m; sml[wid * 2 + 1] = l; }
    __syncthreads();

    float M = -INFINITY;
#pragma unroll
    for (int w = 0; w < 8; w++) M = fmaxf(M, sml[w * 2]);
    float L = 0.f, c0 = 0.f, c1 = 0.f;
#pragma unroll
    for (int w = 0; w < 8; w++) {
        float e = __expf(sml[w * 2] - M);
        L += e * sml[w * 2 + 1];
        c0 += e * sctx[w][t];
        c1 += e * sctx[w][t + 256];
    }
    size_t base = ((size_t)sp * BB + b) * HH;
    g_pctx[base + t] = c0;
    g_pctx[base + t + 256] = c1;
    if (t == 0) {
        g_pml[(sp * BB + b) * 2] = M;
        g_pml[(sp * BB + b) * 2 + 1] = L;
    }
}

// ---------------- mega kernel: cls_h blocks (first) + attention blocks ------
__global__ void __launch_bounds__(256) k_mega(const float* __restrict__ enc,
                                              const float* __restrict__ W_cls,
                                              float* __restrict__ out) {
    __shared__ float sm[6400];   // 25.6 KB, both roles fit
    if (blockIdx.x < NCLS_TILES) {
        // h-half of classifier: K = 0..512 of [h | ctx]
        cls_body<false>(sm, g_A, W_cls, nullptr, out, blockIdx.x * 128, 512);
    } else {
        attn_body(sm, enc, blockIdx.x - NCLS_TILES);
    }
}

// ---------------- ctx-half of classifier (after comb) ----------------
__global__ void __launch_bounds__(256) k_cls_ctx(const float* __restrict__ W_cls,
                                                 const float* __restrict__ b_cls,
                                                 float* __restrict__ out) {
    __shared__ float sm[6400];
    cls_body<true>(sm, g_A + 512, W_cls + 512, b_cls, out, blockIdx.x * 128, 512);
}

// ---------------- combine splits ----------------
__global__ void k_comb() {
    int b = blockIdx.x, t = threadIdx.x;
    __shared__ float sm[NSPLIT], sl[NSPLIT];
    if (t < NSPLIT) {
        sm[t] = g_pml[(t * BB + b) * 2];
        sl[t] = g_pml[(t * BB + b) * 2 + 1];
    }
    __syncthreads();
    float M = -INFINITY;
#pragma unroll
    for (int i = 0; i < NSPLIT; i++) M = fmaxf(M, sm[i]);
    float L = 0.f;
#pragma unroll
    for (int i = 0; i < NSPLIT; i++) L += sl[i] * __expf(sm[i] - M);
    float inv = 1.f / L;
    float o0 = 0.f, o1 = 0.f;
#pragma unroll
    for (int i = 0; i < NSPLIT; i++) {
        float w = __expf(sm[i] - M);
        size_t base = ((size_t)i * BB + b) * HH;
        o0 += w * g_pctx[base + t];
        o1 += w * g_pctx[base + t + 256];
    }
    g_A[b * 1024 + 512 + t] = o0 * inv;
    g_A[b * 1024 + 512 + t + 256] = o1 * inv;
}

// ---------------- fused log-softmax ----------------
__global__ void k_lsefix(float* __restrict__ out) {
    const int b = blockIdx.x, t = threadIdx.x;   // 1024 threads
    float4* row = (float4*)(out + (size_t)b * VV);
    __shared__ float red[32];
    __shared__ float sM, sL;
    const int lane = t & 31, wid = t >> 5;

    float mx = -INFINITY;
    for (int i = t; i < VV / 4; i += 1024) {
        float4 v = row[i];
        mx = fmaxf(mx, fmaxf(fmaxf(v.x, v.y), fmaxf(v.z, v.w)));
    }
#pragma unroll
    for (int o = 16; o; o >>= 1) mx = fmaxf(mx, __shfl_xor_sync(0xffffffffu, mx, o));
    if (lane == 0) red[wid] = mx;
    __syncthreads();
    if (t < 32) {
        float q = red[t];
#pragma unroll
        for (int o = 16; o; o >>= 1) q = fmaxf(q, __shfl_xor_sync(0xffffffffu, q, o));
        if (t == 0) sM = q;
    }
    __syncthreads();
    const float M = sM;

    float s = 0.f;
    for (int i = t; i < VV / 4; i += 1024) {
        float4 v = row[i];
        s += __expf(v.x - M) + __expf(v.y - M) + __expf(v.z - M) + __expf(v.w - M);
    }
#pragma unroll
    for (int o = 16; o; o >>= 1) s += __shfl_xor_sync(0xffffffffu, s, o);
    if (lane == 0) red[wid] = s;
    __syncthreads();
    if (t < 32) {
        float q = red[t];
#pragma unroll
        for (int o = 16; o; o >>= 1) q += __shfl_xor_sync(0xffffffffu, q, o);
        if (t == 0) sL = q;
    }
    __syncthreads();
    const float c = M + logf(sL);

    for (int i = t; i < VV / 4; i += 1024) {
        float4 v = row[i];
        v.x -= c; v.y -= c; v.z -= c; v.w -= c;
        row[i] = v;
    }
}

// ---------------- launch ----------------
extern "C" void kernel_launch(void* const* d_in, const int* in_sizes, int n_in,
                              void* d_out, int out_size) {
    const int*   dec_inputs = (const int*)d_in[0];
    const float* enc        = (const float*)d_in[1];
    const float* h0         = (const float*)d_in[2];
    const float* emb        = (const float*)d_in[3];
    const float* W_ih       = (const float*)d_in[4];
    const float* W_hh       = (const float*)d_in[5];
    const float* b_ih       = (const float*)d_in[6];
    const float* b_hh       = (const float*)d_in[7];
    const float* W_attn     = (const float*)d_in[8];
    const float* b_attn     = (const float*)d_in[9];   // cancels in softmax
    const float* W_cls      = (const float*)d_in[10];
    const float* b_cls      = (const float*)d_in[11];
    (void)b_attn; (void)in_sizes; (void)n_in; (void)out_size;

    float* out        = (float*)d_out;
    float* out_hidden = (float*)d_out + (size_t)BB * VV;

    k_embed<<<BB, 128>>>(dec_inputs, emb);
    k_gru<<<dim3(24, 2), 128>>>(h0, W_ih, W_hh, b_ih, b_hh);
    k_gates<<<BB * HH / 256, 256>>>(h0, out_hidden);
    k_u<<<8, 128>>>(W_attn);
    k_mega<<<MEGA_BLOCKS, 256>>>(enc, W_cls, out);
    k_comb<<<BB, 256>>>();
    k_cls_ctx<<<NCLS_TILES, 256>>>(W_cls, b_cls, out);
    k_lsefix<<<BB, 1024>>>(out);
}